// round 5
// baseline (speedup 1.0000x reference)
#include <cuda_runtime.h>
#include <stdint.h>

// Real spherical harmonics up to L=8. Output = concat of 9 parts; part l at
// element offset N*l*l, row i at i*(2l+1), column (l+m), m=-l..l.
//
// Single-pass smem staging of l=1..8 (40 KB), one barrier, then the epilogue
// is offloaded to TMA: 8x cp.async.bulk shared::cta -> global (bulk_group).
// This removes all LDS+STG wavefronts and SM store-issue cost from the
// critical path; the TMA engine drains smem while the scheduler runs other
// CTAs. l=0 is a direct stride-1 store.

static constexpr double PI_D = 3.141592653589793238462643383279502884;

constexpr double csqrt(double x) {
    double g = (x > 1.0) ? x : 1.0;
    for (int i = 0; i < 200; ++i) g = 0.5 * (g + x / g);
    return g;
}
constexpr double cfact(int n) {
    double r = 1.0;
    for (int i = 2; i <= n; ++i) r *= (double)i;
    return r;
}

struct NormTab { float v[45]; };
constexpr NormTab make_norms() {
    NormTab t{};
    for (int l = 0; l <= 8; ++l)
        for (int m = 0; m <= l; ++m) {
            double n = csqrt((2.0 * l + 1.0) / (4.0 * PI_D) * cfact(l - m) / cfact(l + m));
            if (m > 0) n *= csqrt(2.0);
            t.v[l * (l + 1) / 2 + m] = (float)n;
        }
    return t;
}
__constant__ NormTab g_norm = make_norms();

static constexpr int T = 128;   // threads per block

__device__ __forceinline__ uint32_t smem_u32(const void* p) {
    uint32_t a;
    asm("{ .reg .u64 t; cvta.to.shared.u64 t, %1; cvt.u32.u64 %0, t; }"
        : "=r"(a) : "l"(p));
    return a;
}

__global__ __launch_bounds__(T)
void sph_l8_tma_kernel(const float* __restrict__ R, float* __restrict__ out, int N) {
    __shared__ float buf[T * 80];   // l=1..8: segment l at float offset T*(l*l-1)

    const int tid = threadIdx.x;
    const int blockStart = blockIdx.x * T;
    const int i = blockStart + tid;
    const int valid = min(T, N - blockStart);

    float x, y, z;
    if (i < N) {
        x = R[3 * i + 0];
        y = R[3 * i + 1];
        z = R[3 * i + 2];
        float inv = rsqrtf(fmaf(x, x, fmaf(y, y, z * z)));
        x *= inv; y *= inv; z *= inv;
    } else {
        x = 0.0f; y = 0.0f; z = 1.0f;
    }

    // A[m] + i B[m] = (x + i y)^m
    float A[9], B[9], p1[9], p2[9];
    A[0] = 1.0f; B[0] = 0.0f;
#pragma unroll
    for (int m = 1; m <= 8; ++m) {
        A[m] = x * A[m - 1] - y * B[m - 1];
        B[m] = x * B[m - 1] + y * A[m - 1];
    }
    constexpr float PMM[9] = {1.f, 1.f, 3.f, 15.f, 105.f, 945.f,
                              10395.f, 135135.f, 2027025.f};

    // l = 0: direct, stride-1
    if (i < N) out[i] = g_norm.v[0];
    p2[0] = 0.0f; p1[0] = PMM[0];

#pragma unroll
    for (int l = 1; l <= 8; ++l) {
        const int W = 2 * l + 1;
        float* row = buf + T * (l * l - 1) + tid * W;
#pragma unroll
        for (int m = 0; m <= l; ++m) {
            float p;
            if (l == m) {
                p = PMM[m];
                p2[m] = 0.0f;
            } else if (l == m + 1) {
                p = (float)(2 * m + 1) * z * p1[m];
                p2[m] = p1[m];
            } else {
                p = ((float)(2 * l - 1) * z * p1[m] - (float)(l + m - 1) * p2[m])
                    * (1.0f / (float)(l - m));
                p2[m] = p1[m];
            }
            p1[m] = p;
            const float c = g_norm.v[l * (l + 1) / 2 + m];
            if (m == 0) {
                row[l] = c * p;
            } else {
                row[l + m] = c * p * A[m];
                row[l - m] = c * p * B[m];
            }
        }
    }
    __syncthreads();

    if (valid == T) {
        // TMA bulk-store epilogue (single elected thread)
        if (tid == 0) {
            asm volatile("fence.proxy.async.shared::cta;" ::: "memory");
#pragma unroll
            for (int l = 1; l <= 8; ++l) {
                const int W = 2 * l + 1;
                float* dst = out + (size_t)N * (size_t)(l * l)
                                 + (size_t)blockStart * (size_t)W;
                uint32_t src = smem_u32(buf + T * (l * l - 1));
                uint32_t bytes = (uint32_t)(T * W * 4);   // 512*W, 16B multiple
                asm volatile(
                    "cp.async.bulk.global.shared::cta.bulk_group [%0], [%1], %2;"
                    :: "l"(dst), "r"(src), "r"(bytes) : "memory");
            }
            asm volatile("cp.async.bulk.commit_group;" ::: "memory");
            asm volatile("cp.async.bulk.wait_group 0;" ::: "memory");
        }
    } else {
        // tail block: scalar coalesced fallback
#pragma unroll
        for (int l = 1; l <= 8; ++l) {
            const int W = 2 * l + 1;
            float* dst = out + (size_t)N * (size_t)(l * l)
                             + (size_t)blockStart * (size_t)W;
            const float* src = buf + T * (l * l - 1);
            const int nf = valid * W;
            for (int j = tid; j < nf; j += T) dst[j] = src[j];
        }
    }
}

extern "C" void kernel_launch(void* const* d_in, const int* in_sizes, int n_in,
                              void* d_out, int out_size) {
    const float* R = (const float*)d_in[0];
    float* out = (float*)d_out;
    int N = in_sizes[0] / 3;
    int blocks = (N + T - 1) / T;
    sph_l8_tma_kernel<<<blocks, T>>>(R, out, N);
}

// round 6
// speedup vs baseline: 1.1352x; 1.1352x over previous
#include <cuda_runtime.h>
#include <stdint.h>

// Real spherical harmonics up to L=8. Output = concat of 9 parts; part l at
// element offset N*l*l, row i at i*(2l+1), column (l+m), m=-l..l.
//
// Two-pass smem staging at T=256 for longer contiguous DRAM store runs
// (3-17 KB per segment per block), float4 __stcs coalesced epilogue.
//   pass A: l=1..5 (35 floats/pt, 35 KB)   [l=0 stored direct, stride-1]
//   pass B: l=6..8 (45 floats/pt, 45 KB)

static constexpr double PI_D = 3.141592653589793238462643383279502884;

constexpr double csqrt(double x) {
    double g = (x > 1.0) ? x : 1.0;
    for (int i = 0; i < 200; ++i) g = 0.5 * (g + x / g);
    return g;
}
constexpr double cfact(int n) {
    double r = 1.0;
    for (int i = 2; i <= n; ++i) r *= (double)i;
    return r;
}

struct NormTab { float v[45]; };
constexpr NormTab make_norms() {
    NormTab t{};
    for (int l = 0; l <= 8; ++l)
        for (int m = 0; m <= l; ++m) {
            double n = csqrt((2.0 * l + 1.0) / (4.0 * PI_D) * cfact(l - m) / cfact(l + m));
            if (m > 0) n *= csqrt(2.0);
            t.v[l * (l + 1) / 2 + m] = (float)n;
        }
    return t;
}
__constant__ NormTab g_norm = make_norms();

static constexpr int T = 256;            // threads per block
static constexpr int BUF_F = 45;         // max floats/point staged per pass

__device__ __forceinline__ constexpr int seg_off(int l, int l_first) {
    return l * l - l_first * l_first;    // sum of (2k+1), k=l_first..l-1
}

extern __shared__ float buf[];           // T * BUF_F floats (dynamic: 45 KB)

__global__ __launch_bounds__(T)
void sph_l8_t256_kernel(const float* __restrict__ R, float* __restrict__ out, int N) {
    const int tid = threadIdx.x;
    const int blockStart = blockIdx.x * T;
    const int i = blockStart + tid;
    const int valid = min(T, N - blockStart);

    float x, y, z;
    if (i < N) {
        x = R[3 * i + 0];
        y = R[3 * i + 1];
        z = R[3 * i + 2];
        float inv = rsqrtf(fmaf(x, x, fmaf(y, y, z * z)));
        x *= inv; y *= inv; z *= inv;
    } else {
        x = 0.0f; y = 0.0f; z = 1.0f;
    }

    float A[9], B[9], p1[9], p2[9];
    A[0] = 1.0f; B[0] = 0.0f;
#pragma unroll
    for (int m = 1; m <= 8; ++m) {
        A[m] = x * A[m - 1] - y * B[m - 1];
        B[m] = x * B[m - 1] + y * A[m - 1];
    }
    constexpr float PMM[9] = {1.f, 1.f, 3.f, 15.f, 105.f, 945.f,
                              10395.f, 135135.f, 2027025.f};

    // l = 0: direct, stride-1
    if (i < N) out[i] = g_norm.v[0];
    p2[0] = 0.0f; p1[0] = PMM[0];

    // ================= PASS A: l = 1..5 =================
#pragma unroll
    for (int l = 1; l <= 5; ++l) {
        const int W = 2 * l + 1;
        float* row = buf + T * seg_off(l, 1) + tid * W;
#pragma unroll
        for (int m = 0; m <= l; ++m) {
            float p;
            if (l == m) {
                p = PMM[m];
                p2[m] = 0.0f;
            } else if (l == m + 1) {
                p = (float)(2 * m + 1) * z * p1[m];
                p2[m] = p1[m];
            } else {
                p = ((float)(2 * l - 1) * z * p1[m] - (float)(l + m - 1) * p2[m])
                    * (1.0f / (float)(l - m));
                p2[m] = p1[m];
            }
            p1[m] = p;
            const float c = g_norm.v[l * (l + 1) / 2 + m];
            if (m == 0) {
                row[l] = c * p;
            } else {
                row[l + m] = c * p * A[m];
                row[l - m] = c * p * B[m];
            }
        }
    }
    __syncthreads();

#pragma unroll
    for (int l = 1; l <= 5; ++l) {
        const int W = 2 * l + 1;
        float* dst = out + (size_t)N * (size_t)(l * l)
                         + (size_t)blockStart * (size_t)W;
        const float* src = buf + T * seg_off(l, 1);
        if (valid == T) {
            float4* __restrict__ d4 = (float4*)dst;       // N*l*l*4 and 1024*W are 16B multiples
            const float4* __restrict__ s4 = (const float4*)src;
            const int n4 = (T * W) >> 2;                  // 64*W
#pragma unroll
            for (int j = tid; j < n4; j += T) __stcs(&d4[j], s4[j]);
        } else {
            const int nf = valid * W;
            for (int j = tid; j < nf; j += T) dst[j] = src[j];
        }
    }
    __syncthreads();

    // ================= PASS B: l = 6..8 =================
#pragma unroll
    for (int l = 6; l <= 8; ++l) {
        const int W = 2 * l + 1;
        float* row = buf + T * seg_off(l, 6) + tid * W;
#pragma unroll
        for (int m = 0; m <= l; ++m) {
            float p;
            if (l == m) {
                p = PMM[m];
                p2[m] = 0.0f;
            } else if (l == m + 1) {
                p = (float)(2 * m + 1) * z * p1[m];
                p2[m] = p1[m];
            } else {
                p = ((float)(2 * l - 1) * z * p1[m] - (float)(l + m - 1) * p2[m])
                    * (1.0f / (float)(l - m));
                p2[m] = p1[m];
            }
            p1[m] = p;
            const float c = g_norm.v[l * (l + 1) / 2 + m];
            if (m == 0) {
                row[l] = c * p;
            } else {
                row[l + m] = c * p * A[m];
                row[l - m] = c * p * B[m];
            }
        }
    }
    __syncthreads();

#pragma unroll
    for (int l = 6; l <= 8; ++l) {
        const int W = 2 * l + 1;
        float* dst = out + (size_t)N * (size_t)(l * l)
                         + (size_t)blockStart * (size_t)W;
        const float* src = buf + T * seg_off(l, 6);
        if (valid == T) {
            float4* __restrict__ d4 = (float4*)dst;
            const float4* __restrict__ s4 = (const float4*)src;
            const int n4 = (T * W) >> 2;
#pragma unroll
            for (int j = tid; j < n4; j += T) __stcs(&d4[j], s4[j]);
        } else {
            const int nf = valid * W;
            for (int j = tid; j < nf; j += T) dst[j] = src[j];
        }
    }
}

extern "C" void kernel_launch(void* const* d_in, const int* in_sizes, int n_in,
                              void* d_out, int out_size) {
    const float* R = (const float*)d_in[0];
    float* out = (float*)d_out;
    int N = in_sizes[0] / 3;
    int blocks = (N + T - 1) / T;
    size_t smem = (size_t)T * BUF_F * sizeof(float);     // 46080 B
    cudaFuncSetAttribute(sph_l8_t256_kernel,
                         cudaFuncAttributeMaxDynamicSharedMemorySize, (int)smem);
    sph_l8_t256_kernel<<<blocks, T, smem>>>(R, out, N);
}

// round 7
// speedup vs baseline: 1.1487x; 1.0118x over previous
#include <cuda_runtime.h>
#include <stdint.h>

// Real spherical harmonics up to L=8. Output = concat of 9 parts; part l at
// element offset N*l*l, row i at i*(2l+1), column (l+m), m=-l..l.
//
// Single-barrier full staging (l=1..8, 80 KB dynamic smem) at T=256:
//  - one __syncthreads total; compute phase fully decoupled from copy phase
//  - copy phase: 8 coalesced float4 __stcs loops, largest segment first,
//    each block's per-segment run is 4..17 KB contiguous in DRAM
//  - l=0 stored direct (stride-1, naturally coalesced)

static constexpr double PI_D = 3.141592653589793238462643383279502884;

constexpr double csqrt(double x) {
    double g = (x > 1.0) ? x : 1.0;
    for (int i = 0; i < 200; ++i) g = 0.5 * (g + x / g);
    return g;
}
constexpr double cfact(int n) {
    double r = 1.0;
    for (int i = 2; i <= n; ++i) r *= (double)i;
    return r;
}

struct NormTab { float v[45]; };
constexpr NormTab make_norms() {
    NormTab t{};
    for (int l = 0; l <= 8; ++l)
        for (int m = 0; m <= l; ++m) {
            double n = csqrt((2.0 * l + 1.0) / (4.0 * PI_D) * cfact(l - m) / cfact(l + m));
            if (m > 0) n *= csqrt(2.0);
            t.v[l * (l + 1) / 2 + m] = (float)n;
        }
    return t;
}
__constant__ NormTab g_norm = make_norms();

static constexpr int T = 256;          // threads per block
static constexpr int STAGE_F = 80;     // floats/point staged (l=1..8)

extern __shared__ float buf[];         // T * STAGE_F floats = 80 KB

__global__ __launch_bounds__(T)
void sph_l8_onebar256_kernel(const float* __restrict__ R, float* __restrict__ out, int N) {
    const int tid = threadIdx.x;
    const int blockStart = blockIdx.x * T;
    const int i = blockStart + tid;
    const int valid = min(T, N - blockStart);

    float x, y, z;
    if (i < N) {
        x = R[3 * i + 0];
        y = R[3 * i + 1];
        z = R[3 * i + 2];
        float inv = rsqrtf(fmaf(x, x, fmaf(y, y, z * z)));
        x *= inv; y *= inv; z *= inv;
    } else {
        x = 0.0f; y = 0.0f; z = 1.0f;
    }

    // A[m] + i B[m] = (x + i y)^m
    float A[9], B[9], p1[9], p2[9];
    A[0] = 1.0f; B[0] = 0.0f;
#pragma unroll
    for (int m = 1; m <= 8; ++m) {
        A[m] = x * A[m - 1] - y * B[m - 1];
        B[m] = x * B[m - 1] + y * A[m - 1];
    }
    constexpr float PMM[9] = {1.f, 1.f, 3.f, 15.f, 105.f, 945.f,
                              10395.f, 135135.f, 2027025.f};

    // l = 0: direct, stride-1
    if (i < N) out[i] = g_norm.v[0];
    p2[0] = 0.0f; p1[0] = PMM[0];

    // ---- compute + stage l = 1..8 (segment l at float offset T*(l*l-1)) ----
#pragma unroll
    for (int l = 1; l <= 8; ++l) {
        const int W = 2 * l + 1;
        float* row = buf + T * (l * l - 1) + tid * W;
#pragma unroll
        for (int m = 0; m <= l; ++m) {
            float p;
            if (l == m) {
                p = PMM[m];
                p2[m] = 0.0f;
            } else if (l == m + 1) {
                p = (float)(2 * m + 1) * z * p1[m];
                p2[m] = p1[m];
            } else {
                p = ((float)(2 * l - 1) * z * p1[m] - (float)(l + m - 1) * p2[m])
                    * (1.0f / (float)(l - m));
                p2[m] = p1[m];
            }
            p1[m] = p;
            const float c = g_norm.v[l * (l + 1) / 2 + m];
            if (m == 0) {
                row[l] = c * p;
            } else {
                row[l + m] = c * p * A[m];
                row[l - m] = c * p * B[m];
            }
        }
    }
    __syncthreads();

    // ---- copy phase: largest segments first, no barriers in between ----
#pragma unroll
    for (int k = 0; k < 8; ++k) {
        const int l = 8 - k;               // 8,7,...,1
        const int W = 2 * l + 1;
        float* dst = out + (size_t)N * (size_t)(l * l)
                         + (size_t)blockStart * (size_t)W;
        const float* src = buf + T * (l * l - 1);
        if (valid == T) {
            float4* __restrict__ d4 = (float4*)dst;       // 16B-aligned: 4*N*l*l and 1024*W
            const float4* __restrict__ s4 = (const float4*)src;
            const int n4 = (T * W) >> 2;                  // 64*W
#pragma unroll
            for (int j = tid; j < n4; j += T) __stcs(&d4[j], s4[j]);
        } else {
            const int nf = valid * W;
            for (int j = tid; j < nf; j += T) dst[j] = src[j];
        }
    }
}

extern "C" void kernel_launch(void* const* d_in, const int* in_sizes, int n_in,
                              void* d_out, int out_size) {
    const float* R = (const float*)d_in[0];
    float* out = (float*)d_out;
    int N = in_sizes[0] / 3;
    int blocks = (N + T - 1) / T;
    size_t smem = (size_t)T * STAGE_F * sizeof(float);   // 81920 B
    cudaFuncSetAttribute(sph_l8_onebar256_kernel,
                         cudaFuncAttributeMaxDynamicSharedMemorySize, (int)smem);
    sph_l8_onebar256_kernel<<<blocks, T, smem>>>(R, out, N);
}